// round 4
// baseline (speedup 1.0000x reference)
#include <cuda_runtime.h>
#include <math.h>

#define HWSZ 9216
#define GH 96
#define GW 96
#define NTHREADS 1024
#define PPT (HWSZ / NTHREADS)   // 9 pixels per thread, exact
#define NBLOCKS 16

// scratch for the 16 directed distances (8 samples x 2 directions)
__device__ float    g_dir[NBLOCKS];
__device__ unsigned g_count = 0;   // self-resetting completion counter

// One block per (sample, direction).
//   dir 0: src = A & ~B, tgt = B   (distA)
//   dir 1: src = ~A & B, tgt = A   (distB)
// Row-bitmask EDT: 1D horizontal distance from 96-bit row masks via ffs/clz
// (no sequential scan), then exact early-exit ring search along columns.
__global__ __launch_bounds__(NTHREADS) void hausdorff_kernel(
    const float* __restrict__ predict,
    const float* __restrict__ target,
    float* __restrict__ out)
{
    const int n   = blockIdx.x >> 1;
    const int dir = blockIdx.x & 1;
    const int tid = threadIdx.x;

    __shared__ unsigned       s_tgtbits[HWSZ/32];   // 288 words, row-major bits
    __shared__ unsigned       s_srcbits[HWSZ/32];   // 288 words
    __shared__ unsigned short s_rd2[HWSZ];          // squared 1D row distance
    __shared__ int            s_wcount[NTHREADS/32];
    __shared__ int            s_warpmax[NTHREADS/32];

    const float* pa = predict + n * HWSZ;
    const float* pb = target  + n * HWSZ;

    // ---- Phase 1: build row-major bit masks (9 full iterations, no tail) ----
    // rintf(x) > 0.5  <=>  x > 0.5  (round-half-even: 0.5 -> 0), exact for all x.
    int tcount = 0;
    #pragma unroll
    for (int k = 0; k < PPT; k++) {
        const int p = tid + k * NTHREADS;
        bool a = pa[p] > 0.5f;
        bool b = pb[p] > 0.5f;
        bool t = dir ? a : b;
        bool s = dir ? ((!a) && b) : (a && (!b));
        unsigned tb = __ballot_sync(0xffffffffu, t);
        unsigned sb = __ballot_sync(0xffffffffu, s);
        if ((tid & 31) == 0) {               // p stride 1024 keeps word alignment
            s_tgtbits[p >> 5] = tb;
            s_srcbits[p >> 5] = sb;
            tcount += __popc(tb);
        }
    }
    if ((tid & 31) == 0) s_wcount[tid >> 5] = tcount;
    __syncthreads();

    // ---- Phase 2: per-pixel 1D row distance from 96-bit row mask ----
    // nearest set bit >= j via masked ffs; nearest set bit <= j via masked clz.
    #pragma unroll
    for (int k = 0; k < PPT; k++) {
        const int p = tid + k * NTHREADS;
        const int i = p / GW;
        const int j = p - i * GW;
        const unsigned* row = s_tgtbits + i * 3;
        unsigned m0 = row[0], m1 = row[1], m2 = row[2];
        const int w = j >> 5, off = j & 31;
        unsigned hi = 0xffffffffu << off;      // bits >= off within word w
        unsigned lo = (2u << off) - 1u;        // bits <= off (off=31 wraps to ~0)

        unsigned a0 = (w == 0) ? (m0 & hi) : 0u;
        unsigned a1 = (w == 0) ? m1 : ((w == 1) ? (m1 & hi) : 0u);
        unsigned a2 = (w == 2) ? (m2 & hi) : ((w < 2) ? m2 : 0u);
        unsigned b0 = (w == 0) ? (m0 & lo) : m0;
        unsigned b1 = (w == 1) ? (m1 & lo) : ((w > 1) ? m1 : 0u);
        unsigned b2 = (w == 2) ? (m2 & lo) : 0u;

        int up = a0 ? (__ffs(a0) - 1 - j)
               : (a1 ? (31 + __ffs(a1) - j)
               : (a2 ? (63 + __ffs(a2) - j) : 1000));
        int dn = b2 ? (j - 95 + __clz(b2))
               : (b1 ? (j - 63 + __clz(b1))
               : (b0 ? (j - 31 + __clz(b0)) : 1000));
        int d = min(min(up, dn), 255);         // 255 sentinel (empty row); 255^2 fits u16
        s_rd2[p] = (unsigned short)(d * d);    // sentinel 65025 > max true d2 (18050)
    }
    __syncthreads();

    // ---- Phase 3: exact early-exit ring search along columns, src only ----
    int maxd2 = -1;
    #pragma unroll
    for (int k = 0; k < PPT; k++) {
        const int p = tid + k * NTHREADS;
        if ((s_srcbits[p >> 5] >> (p & 31)) & 1u) {
            const int i = p / GW;
            int best = (int)s_rd2[p];
            for (int r = 1; r < GH && r * r < best; r++) {
                int rr = r * r;
                if (i >= r)      best = min(best, rr + (int)s_rd2[p - r * GW]);
                if (i + r < GH)  best = min(best, rr + (int)s_rd2[p + r * GW]);
            }
            maxd2 = max(maxd2, best);
        }
    }

    // ---- Phase 4: block max-reduction + fused finalize ----
    #pragma unroll
    for (int off = 16; off > 0; off >>= 1)
        maxd2 = max(maxd2, __shfl_xor_sync(0xffffffffu, maxd2, off));
    if ((tid & 31) == 0) s_warpmax[tid >> 5] = maxd2;
    __syncthreads();

    if (tid == 0) {
        int m = -1, tc = 0;
        #pragma unroll
        for (int w = 0; w < NTHREADS / 32; w++) {
            m  = max(m, s_warpmax[w]);
            tc += s_wcount[w];
        }
        float val;
        if (m < 0)        val = 0.0f;                      // src empty
        else if (tc == 0) val = 1e9f;                      // src nonempty, tgt empty
        else              val = sqrtf((float)m) * (1.0f / 96.0f);
        g_dir[blockIdx.x] = val;

        // fused finalize: last block computes the mean
        __threadfence();
        unsigned done = atomicAdd(&g_count, 1);
        if (done == NBLOCKS - 1) {
            g_count = 0;                       // reset for next graph replay
            __threadfence();
            const volatile float* gd = g_dir;
            float s = 0.0f;
            #pragma unroll
            for (int q = 0; q < 8; q++)
                s += fmaxf(gd[2 * q], gd[2 * q + 1]);
            out[0] = s * 0.125f;
        }
    }
}

extern "C" void kernel_launch(void* const* d_in, const int* in_sizes, int n_in,
                              void* d_out, int out_size)
{
    const float* predict = (const float*)d_in[0];
    const float* target  = (const float*)d_in[1];
    hausdorff_kernel<<<NBLOCKS, NTHREADS>>>(predict, target, (float*)d_out);
}

// round 5
// speedup vs baseline: 1.4428x; 1.4428x over previous
#include <cuda_runtime.h>
#include <math.h>

#define HWSZ   9216
#define GH     96
#define GW     96
#define NPAIR  16          // 8 samples x 2 directions
#define BANDS  8
#define RPB    (GH / BANDS)        // 12 rows per band
#define BPX    (RPB * GW)          // 1152 pixels per band
#define NT     384
#define PPT    (BPX / NT)          // 3 pixels per thread, exact
#define NBLK   (NPAIR * BANDS)     // 128 blocks

// global scratch (per-pair squared 1D row distance) + control state
__device__ unsigned short g_rd2[NPAIR][HWSZ];
__device__ int      g_pairmax[NPAIR] = {-1,-1,-1,-1,-1,-1,-1,-1,
                                        -1,-1,-1,-1,-1,-1,-1,-1};
__device__ int      g_tcnt[NPAIR];        // zero-init
__device__ unsigned g_c1[NPAIR];          // per-pair band barrier, zero-init
__device__ unsigned g_c2 = 0;             // global completion counter

// pair = 2*sample + dir.
//   dir 0: src = A & ~B, tgt = B   (distA)
//   dir 1: src = ~A & B, tgt = A   (distB)
__global__ __launch_bounds__(NT) void hausdorff_kernel(
    const float* __restrict__ predict,
    const float* __restrict__ target,
    float* __restrict__ out)
{
    const int pair = blockIdx.x >> 3;
    const int band = blockIdx.x & 7;
    const int dir  = pair & 1;
    const int tid  = threadIdx.x;
    const int base = band * BPX;           // absolute pixel base of this band

    __shared__ unsigned       s_tgtbits[BPX / 32];  // 36 words (12 rows x 96 bits)
    __shared__ unsigned       s_srcbits[BPX / 32];  // 36 words
    __shared__ unsigned short s_rd2[HWSZ];          // full-tile rd2 (18 KB)
    __shared__ int            s_warpmax[NT / 32];

    const float* pa = predict + (pair >> 1) * HWSZ;
    const float* pb = target  + (pair >> 1) * HWSZ;

    // ---- Phase 1: masks for this band (rintf(x)>0.5 <=> x>0.5, half-even) ----
    int tcount = 0;
    #pragma unroll
    for (int k = 0; k < PPT; k++) {
        const int lp = tid + k * NT;       // 0..1151, lane0 word-aligned
        const int p  = base + lp;
        bool a = pa[p] > 0.5f;
        bool b = pb[p] > 0.5f;
        bool t = dir ? a : b;
        bool s = dir ? ((!a) && b) : (a && (!b));
        unsigned tb = __ballot_sync(0xffffffffu, t);
        unsigned sb = __ballot_sync(0xffffffffu, s);
        if ((tid & 31) == 0) {
            s_tgtbits[lp >> 5] = tb;
            s_srcbits[lp >> 5] = sb;
            tcount += __popc(tb);
        }
    }
    if ((tid & 31) == 0 && tcount) atomicAdd(&g_tcnt[pair], tcount);
    __syncthreads();

    // ---- Phase 2: 1D row distance^2 from 96-bit row masks -> global ----
    #pragma unroll
    for (int k = 0; k < PPT; k++) {
        const int lp = tid + k * NT;
        const int li = lp / GW;
        const int j  = lp - li * GW;
        const unsigned* row = s_tgtbits + li * 3;
        unsigned m0 = row[0], m1 = row[1], m2 = row[2];
        const int w = j >> 5, off = j & 31;
        unsigned hi = 0xffffffffu << off;
        unsigned lo = (2u << off) - 1u;

        unsigned a0 = (w == 0) ? (m0 & hi) : 0u;
        unsigned a1 = (w == 0) ? m1 : ((w == 1) ? (m1 & hi) : 0u);
        unsigned a2 = (w == 2) ? (m2 & hi) : ((w < 2) ? m2 : 0u);
        unsigned b0 = (w == 0) ? (m0 & lo) : m0;
        unsigned b1 = (w == 1) ? (m1 & lo) : ((w > 1) ? m1 : 0u);
        unsigned b2 = (w == 2) ? (m2 & lo) : 0u;

        int up = a0 ? (__ffs(a0) - 1 - j)
               : (a1 ? (31 + __ffs(a1) - j)
               : (a2 ? (63 + __ffs(a2) - j) : 1000));
        int dn = b2 ? (j - 95 + __clz(b2))
               : (b1 ? (j - 63 + __clz(b1))
               : (b0 ? (j - 31 + __clz(b0)) : 1000));
        int d = min(min(up, dn), 255);              // empty-row sentinel
        g_rd2[pair][base + lp] = (unsigned short)(d * d);
    }

    // ---- per-pair barrier: all 8 bands' rd2 visible ----
    __syncthreads();
    if (tid == 0) {
        __threadfence();                            // release rd2 writes
        atomicAdd(&g_c1[pair], 1u);
        volatile unsigned* c = &g_c1[pair];
        while (*c < BANDS) { }
        __threadfence();                            // acquire
    }
    __syncthreads();

    // ---- Phase 3a: pull full rd2 tile L2 -> smem (L1-bypass loads) ----
    const unsigned* gsrc = (const unsigned*)&g_rd2[pair][0];
    #pragma unroll
    for (int q = tid; q < HWSZ / 2; q += NT)        // 12 iterations
        ((unsigned*)s_rd2)[q] = __ldcg(gsrc + q);
    __syncthreads();

    // ---- Phase 3b: exact early-exit ring search (columns), src px only ----
    int maxd2 = -1;
    #pragma unroll
    for (int k = 0; k < PPT; k++) {
        const int lp = tid + k * NT;
        if ((s_srcbits[lp >> 5] >> (lp & 31)) & 1u) {
            const int p = base + lp;
            const int i = p / GW;                   // absolute row
            int best = (int)s_rd2[p];
            for (int r = 1; r < GH && r * r < best; r++) {
                int rr = r * r;
                if (i >= r)      best = min(best, rr + (int)s_rd2[p - r * GW]);
                if (i + r < GH)  best = min(best, rr + (int)s_rd2[p + r * GW]);
            }
            maxd2 = max(maxd2, best);
        }
    }

    // ---- Phase 4: block reduce -> per-pair atomicMax -> last-block finalize ----
    #pragma unroll
    for (int off = 16; off > 0; off >>= 1)
        maxd2 = max(maxd2, __shfl_xor_sync(0xffffffffu, maxd2, off));
    if ((tid & 31) == 0) s_warpmax[tid >> 5] = maxd2;
    __syncthreads();

    if (tid == 0) {
        int m = -1;
        #pragma unroll
        for (int w = 0; w < NT / 32; w++) m = max(m, s_warpmax[w]);
        if (m >= 0) atomicMax(&g_pairmax[pair], m);

        __threadfence();
        unsigned done = atomicAdd(&g_c2, 1u);
        if (done == NBLK - 1) {                     // last block finalizes
            __threadfence();
            const volatile int* pm = g_pairmax;
            const volatile int* tc = g_tcnt;
            float s = 0.0f;
            #pragma unroll
            for (int q = 0; q < 8; q++) {
                float v0, v1;
                int m0 = pm[2 * q],     t0 = tc[2 * q];
                int m1 = pm[2 * q + 1], t1 = tc[2 * q + 1];
                v0 = (m0 < 0) ? 0.0f : ((t0 == 0) ? 1e9f : sqrtf((float)m0) * (1.0f / 96.0f));
                v1 = (m1 < 0) ? 0.0f : ((t1 == 0) ? 1e9f : sqrtf((float)m1) * (1.0f / 96.0f));
                s += fmaxf(v0, v1);
            }
            out[0] = s * 0.125f;
            // reset all control state for the next graph replay
            #pragma unroll
            for (int q = 0; q < NPAIR; q++) {
                g_pairmax[q] = -1;
                g_tcnt[q]    = 0;
                g_c1[q]      = 0;
            }
            g_c2 = 0;
            __threadfence();
        }
    }
}

extern "C" void kernel_launch(void* const* d_in, const int* in_sizes, int n_in,
                              void* d_out, int out_size)
{
    const float* predict = (const float*)d_in[0];
    const float* target  = (const float*)d_in[1];
    hausdorff_kernel<<<NBLK, NT>>>(predict, target, (float*)d_out);
}

// round 6
// speedup vs baseline: 1.5363x; 1.0648x over previous
#include <cuda_runtime.h>
#include <math.h>

#define HWSZ   9216
#define GH     96
#define GW     96
#define NPAIR  16                  // 8 samples x 2 directions
#define BANDS  8
#define RPB    (GH / BANDS)        // 12 rows per band
#define BPX    (RPB * GW)          // 1152 pixels per band
#define NT     384
#define PPT    (BPX / NT)          // 3 pixels per thread, exact
#define NBLK   (NPAIR * BANDS)     // 128 blocks

// global scratch (per-pair squared 1D row distance) + control state
__device__ unsigned short g_rd2[NPAIR][HWSZ];
__device__ int      g_pairmax[NPAIR] = {-1,-1,-1,-1,-1,-1,-1,-1,
                                        -1,-1,-1,-1,-1,-1,-1,-1};
__device__ int      g_tcnt[NPAIR];        // zero-init
__device__ unsigned g_c1[NPAIR];          // per-pair band barrier, zero-init
__device__ unsigned g_c2 = 0;             // global completion counter

// pair = 2*sample + dir.
//   dir 0: src = A & ~B, tgt = B   (distA)
//   dir 1: src = ~A & B, tgt = A   (distB)
__global__ __launch_bounds__(NT) void hausdorff_kernel(
    const float* __restrict__ predict,
    const float* __restrict__ target,
    float* __restrict__ out)
{
    const int pair = blockIdx.x >> 3;
    const int band = blockIdx.x & 7;
    const int dir  = pair & 1;
    const int tid  = threadIdx.x;
    const int base = band * BPX;           // absolute pixel base of this band

    // padded row-bit layout: 8 words/row = [0,0, w0,w1,w2, 0,0,0]; row base = i*8+2
    __shared__ unsigned       s_tgtpad[RPB * 8];    // 96 words
    __shared__ unsigned       s_srcbits[BPX / 32];  // 36 words
    __shared__ unsigned short s_rd2[HWSZ];          // full-tile rd2 (18 KB)
    __shared__ int            s_warpmax[NT / 32];

    const float* pa = predict + (pair >> 1) * HWSZ;
    const float* pb = target  + (pair >> 1) * HWSZ;

    // zero the 5 pad words per row (disjoint from ballot-written data words)
    if (tid < RPB * 5) {
        int r = tid / 5, pi = tid % 5;
        s_tgtpad[r * 8 + ((pi < 2) ? pi : pi + 3)] = 0u;
    }

    // ---- Phase 1: masks for this band (rintf(x)>0.5 <=> x>0.5, half-even) ----
    int tcount = 0;
    #pragma unroll
    for (int k = 0; k < PPT; k++) {
        const int lp = tid + k * NT;       // 0..1151, lane0 word-aligned
        const int p  = base + lp;
        bool a = pa[p] > 0.5f;
        bool b = pb[p] > 0.5f;
        bool t = dir ? a : b;
        bool s = dir ? ((!a) && b) : (a && (!b));
        unsigned tb = __ballot_sync(0xffffffffu, t);
        unsigned sb = __ballot_sync(0xffffffffu, s);
        if ((tid & 31) == 0) {
            const int ww = lp >> 5;        // 0..35
            const int li = ww / 3, wi = ww - li * 3;
            s_tgtpad[li * 8 + 2 + wi] = tb;
            s_srcbits[ww] = sb;
            tcount += __popc(tb);
        }
    }
    if ((tid & 31) == 0 && tcount) atomicAdd(&g_tcnt[pair], tcount);
    __syncthreads();

    // ---- Phase 2: 1D row distance^2 via padded-row indexed loads + 64-bit scans ----
    #pragma unroll
    for (int k = 0; k < PPT; k++) {
        const int lp = tid + k * NT;
        const int li = lp / GW;
        const int j  = lp - li * GW;
        const int w  = j >> 5, off = j & 31;
        const unsigned* bw = s_tgtpad + li * 8 + 2 + w;   // padded: bw[-2..2] valid
        unsigned d2v = bw[-2], d1v = bw[-1], m = bw[0], u1v = bw[1], u2v = bw[2];
        unsigned hi = 0xffffffffu << off;
        unsigned lo = (2u << off) - 1u;     // off=31 wraps to ~0

        unsigned long long upair = (unsigned long long)(m & hi)
                                 | ((unsigned long long)u1v << 32);
        unsigned long long dpair = (unsigned long long)d1v
                                 | ((unsigned long long)(m & lo) << 32);

        int up = upair ? (w * 32 + __ffsll(upair) - 1 - j)
               : (u2v  ? (w * 32 + 64 + __ffs(u2v) - 1 - j) : 1000);
        int dn = dpair ? (j - (w * 32 - 32 + 63 - __clzll(dpair)))
               : (d2v  ? (j - (w * 32 - 64 + 31 - __clz(d2v))) : 1000);
        int d = min(min(up, dn), 255);              // empty-row sentinel
        g_rd2[pair][base + lp] = (unsigned short)(d * d);
    }

    // ---- per-pair barrier: all 8 bands' rd2 visible ----
    __syncthreads();
    if (tid == 0) {
        __threadfence();                            // release rd2 writes
        atomicAdd(&g_c1[pair], 1u);
        volatile unsigned* c = &g_c1[pair];
        while (*c < BANDS) { }
        __threadfence();                            // acquire
    }
    __syncthreads();

    // ---- Phase 3a: pull full rd2 tile L2 -> smem, 128-bit loads ----
    {
        const uint4* gsrc = (const uint4*)&g_rd2[pair][0];  // 1152 uint4
        uint4* sdst = (uint4*)s_rd2;
        #pragma unroll
        for (int k = 0; k < 3; k++)
            sdst[tid + k * NT] = __ldcg(gsrc + tid + k * NT);
    }
    __syncthreads();

    // ---- Phase 3b: exact early-exit ring search (columns), src px only ----
    int maxd2 = -1;
    #pragma unroll
    for (int k = 0; k < PPT; k++) {
        const int lp = tid + k * NT;
        if ((s_srcbits[lp >> 5] >> (lp & 31)) & 1u) {
            const int p = base + lp;
            const int i = p / GW;                   // absolute row
            int best = (int)s_rd2[p];
            for (int r = 1; r < GH && r * r < best; r++) {
                int rr = r * r;
                if (i >= r)      best = min(best, rr + (int)s_rd2[p - r * GW]);
                if (i + r < GH)  best = min(best, rr + (int)s_rd2[p + r * GW]);
            }
            maxd2 = max(maxd2, best);
        }
    }

    // ---- Phase 4: block reduce -> per-pair atomicMax -> last-block finalize ----
    #pragma unroll
    for (int off = 16; off > 0; off >>= 1)
        maxd2 = max(maxd2, __shfl_xor_sync(0xffffffffu, maxd2, off));
    if ((tid & 31) == 0) s_warpmax[tid >> 5] = maxd2;
    __syncthreads();

    if (tid == 0) {
        int m = -1;
        #pragma unroll
        for (int w = 0; w < NT / 32; w++) m = max(m, s_warpmax[w]);
        if (m >= 0) atomicMax(&g_pairmax[pair], m);

        __threadfence();
        unsigned done = atomicAdd(&g_c2, 1u);
        if (done == NBLK - 1) {                     // last block finalizes
            __threadfence();
            // batched, independent L2 loads (MLP-covered), no volatile serialization
            int pm[NPAIR], tc[NPAIR];
            #pragma unroll
            for (int q = 0; q < NPAIR; q++) {
                pm[q] = __ldcg(&g_pairmax[q]);
                tc[q] = __ldcg(&g_tcnt[q]);
            }
            float s = 0.0f;
            #pragma unroll
            for (int q = 0; q < 8; q++) {
                float v0 = (pm[2*q]   < 0) ? 0.0f : ((tc[2*q]   == 0) ? 1e9f : sqrtf((float)pm[2*q])   * (1.0f/96.0f));
                float v1 = (pm[2*q+1] < 0) ? 0.0f : ((tc[2*q+1] == 0) ? 1e9f : sqrtf((float)pm[2*q+1]) * (1.0f/96.0f));
                s += fmaxf(v0, v1);
            }
            out[0] = s * 0.125f;
            // reset all control state for the next graph replay
            #pragma unroll
            for (int q = 0; q < NPAIR; q++) {
                g_pairmax[q] = -1;
                g_tcnt[q]    = 0;
                g_c1[q]      = 0;
            }
            g_c2 = 0;
            __threadfence();
        }
    }
}

extern "C" void kernel_launch(void* const* d_in, const int* in_sizes, int n_in,
                              void* d_out, int out_size)
{
    const float* predict = (const float*)d_in[0];
    const float* target  = (const float*)d_in[1];
    hausdorff_kernel<<<NBLK, NT>>>(predict, target, (float*)d_out);
}